// round 1
// baseline (speedup 1.0000x reference)
#include <cuda_runtime.h>

// Plenoxel forward: R=4096 rays, S=128 samples/ray, 160^3 grid.
// Inputs (metadata order):
//   d_in[0] ray_origins    float32 [4096,3]
//   d_in[1] ray_directions float32 [4096,3]
//   d_in[2] density        float32 [160,160,160]
//   d_in[3] sh_coeffs      float32 [160,160,160,3,9]
// Output: concat(rgb[4096,3], depth[4096], acc[4096]) = 20480 floats.

#define GRES        160
#define NSAMP       128
#define T_NEAR      0.1f
#define T_FAR       10.0f
#define SPL         4               // samples per lane (32 lanes * 4 = 128)
#define FULLMASK    0xffffffffu

__global__ __launch_bounds__(256) void plenoxel_fwd_kernel(
    const float* __restrict__ ro,
    const float* __restrict__ rd,
    const float* __restrict__ density,
    const float* __restrict__ sh,
    float* __restrict__ out,     // [R*3] rgb, then [R] depth, then [R] acc
    int R)
{
    const int gwarp = (blockIdx.x * blockDim.x + threadIdx.x) >> 5;
    const int lane  = threadIdx.x & 31;
    if (gwarp >= R) return;
    const int r = gwarp;

    // Ray (all lanes load the same 6 floats -> L1 broadcast)
    const float ox = ro[r*3+0], oy = ro[r*3+1], oz = ro[r*3+2];
    const float dx = rd[r*3+0], dy = rd[r*3+1], dz = rd[r*3+2];

    const float dnorm = sqrtf(dx*dx + dy*dy + dz*dz);
    const float inv   = 1.0f / (dnorm + 1e-8f);
    const float nx = dx*inv, ny = dy*inv, nz = dz*inv;

    // SH degree-2 basis (per ray)
    float b[9];
    b[0] =  0.28209479177387814f;
    b[1] = -0.48860251190291987f * ny;
    b[2] =  0.48860251190291987f * nz;
    b[3] = -0.48860251190291987f * nx;
    b[4] =  1.0925484305920792f  * nx * ny;
    b[5] = -1.0925484305920792f  * ny * nz;
    b[6] =  0.31539156525252005f * (2.0f*nz*nz - nx*nx - ny*ny);
    b[7] = -1.0925484305920792f  * nx * nz;
    b[8] =  0.5462742152960396f  * (nx*nx - ny*ny);

    const float dt = (T_FAR - T_NEAR) / (float)(NSAMP - 1);

    float alpha[SPL], c0v[SPL], c1v[SPL], c2v[SPL], tvv[SPL];

    #pragma unroll
    for (int k = 0; k < SPL; k++) {
        const int   s = lane * SPL + k;
        const float t = T_NEAR + dt * (float)s;
        tvv[k] = t;

        // World point -> voxel coords: (p - (-1)) / 2 * 160
        float vx = (ox + t*dx + 1.0f) * 80.0f;
        float vy = (oy + t*dy + 1.0f) * 80.0f;
        float vz = (oz + t*dz + 1.0f) * 80.0f;
        vx = fminf(fmaxf(vx, 0.0f), 159.0f);
        vy = fminf(fmaxf(vy, 0.0f), 159.0f);
        vz = fminf(fmaxf(vz, 0.0f), 159.0f);

        const float fx = floorf(vx), fy = floorf(vy), fz = floorf(vz);
        const int x0 = (int)fx, y0 = (int)fy, z0 = (int)fz;
        const int x1 = min(x0 + 1, GRES - 1);
        const int y1 = min(y0 + 1, GRES - 1);
        const int z1 = min(z0 + 1, GRES - 1);
        const float ddx = vx - fx, ddy = vy - fy, ddz = vz - fz;

        const int   xs[2]  = {x0, x1};
        const int   ys[2]  = {y0, y1};
        const int   zs[2]  = {z0, z1};
        const float wxs[2] = {1.0f - ddx, ddx};
        const float wys[2] = {1.0f - ddy, ddy};
        const float wzs[2] = {1.0f - ddz, ddz};

        float dens = 0.0f, c0 = 0.0f, c1 = 0.0f, c2 = 0.0f;
        #pragma unroll
        for (int ci = 0; ci < 8; ci++) {
            const int ix = ci & 1, iy = (ci >> 1) & 1, iz = (ci >> 2) & 1;
            const float w   = wxs[ix] * wys[iy] * wzs[iz];
            const int   idx = (zs[iz] * GRES + ys[iy]) * GRES + xs[ix];

            dens += w * __ldg(density + idx);

            const float* sp = sh + (size_t)idx * 27;
            float d0 = 0.0f, d1 = 0.0f, d2 = 0.0f;
            #pragma unroll
            for (int j = 0; j < 9; j++) {
                const float bj = b[j];
                d0 += __ldg(sp +      j) * bj;
                d1 += __ldg(sp +  9 + j) * bj;
                d2 += __ldg(sp + 18 + j) * bj;
            }
            c0 += w * d0; c1 += w * d1; c2 += w * d2;
        }

        // Sigmoid colors
        c0v[k] = 1.0f / (1.0f + expf(-c0));
        c1v[k] = 1.0f / (1.0f + expf(-c1));
        c2v[k] = 1.0f / (1.0f + expf(-c2));

        // alpha
        const float dist = ((s == NSAMP - 1) ? 1e10f : dt) * dnorm;
        alpha[k] = 1.0f - expf(-fmaxf(dens, 0.0f) * dist);
    }

    // Transmittance: exclusive cumprod of (1 - alpha + 1e-10) across 128 samples.
    // Local (within-lane) exclusive prefixes + warp-level product scan.
    float lp[SPL];
    float p = 1.0f;
    #pragma unroll
    for (int k = 0; k < SPL; k++) {
        lp[k] = p;
        p *= (1.0f - alpha[k] + 1e-10f);
    }
    // inclusive warp scan of per-lane products
    float incl = p;
    #pragma unroll
    for (int o = 1; o < 32; o <<= 1) {
        const float v = __shfl_up_sync(FULLMASK, incl, o);
        if (lane >= o) incl *= v;
    }
    float excl = __shfl_up_sync(FULLMASK, incl, 1);
    if (lane == 0) excl = 1.0f;

    // Weighted accumulation
    float rgb0 = 0.0f, rgb1 = 0.0f, rgb2 = 0.0f, dep = 0.0f, acc = 0.0f;
    #pragma unroll
    for (int k = 0; k < SPL; k++) {
        const float w = alpha[k] * excl * lp[k];
        rgb0 += w * c0v[k];
        rgb1 += w * c1v[k];
        rgb2 += w * c2v[k];
        dep  += w * tvv[k];
        acc  += w;
    }

    // Warp reduction
    #pragma unroll
    for (int o = 16; o > 0; o >>= 1) {
        rgb0 += __shfl_xor_sync(FULLMASK, rgb0, o);
        rgb1 += __shfl_xor_sync(FULLMASK, rgb1, o);
        rgb2 += __shfl_xor_sync(FULLMASK, rgb2, o);
        dep  += __shfl_xor_sync(FULLMASK, dep,  o);
        acc  += __shfl_xor_sync(FULLMASK, acc,  o);
    }

    if (lane == 0) {
        out[r*3 + 0]     = rgb0;
        out[r*3 + 1]     = rgb1;
        out[r*3 + 2]     = rgb2;
        out[R*3 + r]     = dep;   // depth block
        out[R*4 + r]     = acc;   // acc block
    }
}

extern "C" void kernel_launch(void* const* d_in, const int* in_sizes, int n_in,
                              void* d_out, int out_size)
{
    const float* ro      = (const float*)d_in[0];
    const float* rd      = (const float*)d_in[1];
    const float* density = (const float*)d_in[2];
    const float* sh      = (const float*)d_in[3];
    float* out           = (float*)d_out;

    const int R = in_sizes[0] / 3;          // 4096 rays
    const int warps_per_block = 256 / 32;   // 8 rays per block
    const int blocks = (R + warps_per_block - 1) / warps_per_block;

    plenoxel_fwd_kernel<<<blocks, 256>>>(ro, rd, density, sh, out, R);
}

// round 2
// speedup vs baseline: 1.7761x; 1.7761x over previous
#include <cuda_runtime.h>

// Plenoxel forward: R=4096 rays, S=128 samples/ray, 160^3 grid.
// d_in[0] ray_origins float32[R,3], d_in[1] ray_directions float32[R,3],
// d_in[2] density float32[160^3], d_in[3] sh_coeffs float32[160^3,3,9]
// out: concat(rgb[R,3], depth[R], acc[R])

#define GRES        160
#define NSAMP       128
#define T_NEAR      0.1f
#define T_FAR       10.0f
#define SPL         2               // samples per lane (2 warps/ray * 32 * 2 = 128)
#define FULLMASK    0xffffffffu

__device__ __forceinline__ float getq(const float4 q[8], int u) {
    const int c = u >> 2;
    switch (u & 3) {
        case 0:  return q[c].x;
        case 1:  return q[c].y;
        case 2:  return q[c].z;
        default: return q[c].w;
    }
}

// Accumulate wgt * (SH_row . basis) for the 3 channels.
// Row = floats [4*p_base + O, +27). O is the compile-time misalignment.
template<int O>
__device__ __forceinline__ void sh_row_accum(const float4* __restrict__ p,
                                             const float (&b)[9], float wgt,
                                             float& c0, float& c1, float& c2)
{
    constexpr int NC = (O + 27 + 3) >> 2;   // 7 chunks for O<=1, 8 for O>=2
    float4 q[8];
    #pragma unroll
    for (int i = 0; i < NC; i++) q[i] = __ldg(p + i);

    float d0 = 0.f, d1 = 0.f, d2 = 0.f;
    #pragma unroll
    for (int j = 0; j < 9; j++) {
        const float bj = b[j];
        d0 = fmaf(getq(q, O +      j), bj, d0);
        d1 = fmaf(getq(q, O +  9 + j), bj, d1);
        d2 = fmaf(getq(q, O + 18 + j), bj, d2);
    }
    c0 = fmaf(wgt, d0, c0);
    c1 = fmaf(wgt, d1, c1);
    c2 = fmaf(wgt, d2, c2);
}

__device__ __forceinline__ void sh_accum(const float4* __restrict__ sh4, int idx,
                                         const float (&b)[9], float wgt,
                                         float& c0, float& c1, float& c2)
{
    const int F = idx * 27;
    const float4* p = sh4 + (F >> 2);
    switch (F & 3) {
        case 0:  sh_row_accum<0>(p, b, wgt, c0, c1, c2); break;
        case 1:  sh_row_accum<1>(p, b, wgt, c0, c1, c2); break;
        case 2:  sh_row_accum<2>(p, b, wgt, c0, c1, c2); break;
        default: sh_row_accum<3>(p, b, wgt, c0, c1, c2); break;
    }
}

__global__ __launch_bounds__(128) void plenoxel_fwd_kernel(
    const float* __restrict__ ro,
    const float* __restrict__ rd,
    const float* __restrict__ density,
    const float* __restrict__ sh,
    float* __restrict__ out,
    int R)
{
    const float4* __restrict__ sh4 = (const float4*)sh;

    const int warp = threadIdx.x >> 5;     // 0..3
    const int lane = threadIdx.x & 31;
    const int rib  = warp >> 1;            // ray-in-block 0..1
    const int wir  = warp & 1;             // warp-in-ray  0..1
    const int r    = min(blockIdx.x * 2 + rib, R - 1);

    __shared__ float sProd[2];
    __shared__ float sPart[2][2][5];

    const float ox = ro[r*3+0], oy = ro[r*3+1], oz = ro[r*3+2];
    const float dx = rd[r*3+0], dy = rd[r*3+1], dz = rd[r*3+2];

    const float dnorm = sqrtf(dx*dx + dy*dy + dz*dz);
    const float inv   = 1.0f / (dnorm + 1e-8f);
    const float nx = dx*inv, ny = dy*inv, nz = dz*inv;

    float b[9];
    b[0] =  0.28209479177387814f;
    b[1] = -0.48860251190291987f * ny;
    b[2] =  0.48860251190291987f * nz;
    b[3] = -0.48860251190291987f * nx;
    b[4] =  1.0925484305920792f  * nx * ny;
    b[5] = -1.0925484305920792f  * ny * nz;
    b[6] =  0.31539156525252005f * (2.0f*nz*nz - nx*nx - ny*ny);
    b[7] = -1.0925484305920792f  * nx * nz;
    b[8] =  0.5462742152960396f  * (nx*nx - ny*ny);

    const float dt = (T_FAR - T_NEAR) / (float)(NSAMP - 1);

    float alpha[SPL], c0v[SPL], c1v[SPL], c2v[SPL], tvv[SPL];

    #pragma unroll
    for (int k = 0; k < SPL; k++) {
        const int   s = wir * 64 + lane * SPL + k;
        const float t = T_NEAR + dt * (float)s;
        tvv[k] = t;

        float vx = (ox + t*dx + 1.0f) * 80.0f;
        float vy = (oy + t*dy + 1.0f) * 80.0f;
        float vz = (oz + t*dz + 1.0f) * 80.0f;
        vx = fminf(fmaxf(vx, 0.0f), 159.0f);
        vy = fminf(fmaxf(vy, 0.0f), 159.0f);
        vz = fminf(fmaxf(vz, 0.0f), 159.0f);

        const float fx = floorf(vx), fy = floorf(vy), fz = floorf(vz);
        const int x0 = (int)fx, y0 = (int)fy, z0 = (int)fz;
        const int x1 = min(x0 + 1, GRES - 1);
        const int y1 = min(y0 + 1, GRES - 1);
        const int z1 = min(z0 + 1, GRES - 1);
        const float ddx = vx - fx, ddy = vy - fy, ddz = vz - fz;
        const float wx0 = 1.0f - ddx, wx1 = ddx;
        const int   xd  = x1 - x0;

        float dens = 0.0f, c0 = 0.0f, c1 = 0.0f, c2 = 0.0f;

        #pragma unroll 1
        for (int cz = 0; cz < 2; cz++) {
            const int   zi = cz ? z1 : z0;
            const float wz = cz ? ddz : (1.0f - ddz);
            #pragma unroll 1
            for (int cy = 0; cy < 2; cy++) {
                const int   yi  = cy ? y1 : y0;
                const float wy  = cy ? ddy : (1.0f - ddy);
                const float wyz = wz * wy;
                const int idx0 = (zi * GRES + yi) * GRES + x0;
                const int idx1 = idx0 + xd;

                dens = fmaf(wyz,
                            wx0 * __ldg(density + idx0) + wx1 * __ldg(density + idx1),
                            dens);
                sh_accum(sh4, idx0, b, wyz * wx0, c0, c1, c2);
                sh_accum(sh4, idx1, b, wyz * wx1, c0, c1, c2);
            }
        }

        c0v[k] = 1.0f / (1.0f + expf(-c0));
        c1v[k] = 1.0f / (1.0f + expf(-c1));
        c2v[k] = 1.0f / (1.0f + expf(-c2));

        const float dist = ((s == NSAMP - 1) ? 1e10f : dt) * dnorm;
        alpha[k] = 1.0f - expf(-fmaxf(dens, 0.0f) * dist);
    }

    // Warp-local exclusive cumprod of (1 - alpha + 1e-10) over 64 samples.
    float lp[SPL];
    float p = 1.0f;
    #pragma unroll
    for (int k = 0; k < SPL; k++) {
        lp[k] = p;
        p *= (1.0f - alpha[k] + 1e-10f);
    }
    float incl = p;
    #pragma unroll
    for (int o = 1; o < 32; o <<= 1) {
        const float v = __shfl_up_sync(FULLMASK, incl, o);
        if (lane >= o) incl *= v;
    }
    float excl = __shfl_up_sync(FULLMASK, incl, 1);
    if (lane == 0) excl = 1.0f;
    const float warpProd = __shfl_sync(FULLMASK, incl, 31);

    // Partial sums (warp-local transmittance; warp 1 scaled by warp 0's product later)
    float rgb0 = 0.0f, rgb1 = 0.0f, rgb2 = 0.0f, dep = 0.0f, acc = 0.0f;
    #pragma unroll
    for (int k = 0; k < SPL; k++) {
        const float w = alpha[k] * excl * lp[k];
        rgb0 += w * c0v[k];
        rgb1 += w * c1v[k];
        rgb2 += w * c2v[k];
        dep  += w * tvv[k];
        acc  += w;
    }
    #pragma unroll
    for (int o = 16; o > 0; o >>= 1) {
        rgb0 += __shfl_xor_sync(FULLMASK, rgb0, o);
        rgb1 += __shfl_xor_sync(FULLMASK, rgb1, o);
        rgb2 += __shfl_xor_sync(FULLMASK, rgb2, o);
        dep  += __shfl_xor_sync(FULLMASK, dep,  o);
        acc  += __shfl_xor_sync(FULLMASK, acc,  o);
    }

    if (lane == 0) {
        sPart[rib][wir][0] = rgb0;
        sPart[rib][wir][1] = rgb1;
        sPart[rib][wir][2] = rgb2;
        sPart[rib][wir][3] = dep;
        sPart[rib][wir][4] = acc;
        if (wir == 0) sProd[rib] = warpProd;
    }
    __syncthreads();

    if (wir == 0 && lane == 0) {
        const float P0 = sProd[rib];
        const float o0 = sPart[rib][0][0] + P0 * sPart[rib][1][0];
        const float o1 = sPart[rib][0][1] + P0 * sPart[rib][1][1];
        const float o2 = sPart[rib][0][2] + P0 * sPart[rib][1][2];
        const float od = sPart[rib][0][3] + P0 * sPart[rib][1][3];
        const float oa = sPart[rib][0][4] + P0 * sPart[rib][1][4];
        out[r*3 + 0] = o0;
        out[r*3 + 1] = o1;
        out[r*3 + 2] = o2;
        out[R*3 + r] = od;
        out[R*4 + r] = oa;
    }
}

extern "C" void kernel_launch(void* const* d_in, const int* in_sizes, int n_in,
                              void* d_out, int out_size)
{
    const float* ro      = (const float*)d_in[0];
    const float* rd      = (const float*)d_in[1];
    const float* density = (const float*)d_in[2];
    const float* sh      = (const float*)d_in[3];
    float* out           = (float*)d_out;

    const int R = in_sizes[0] / 3;
    const int blocks = (R + 1) / 2;   // 2 rays per 128-thread block

    plenoxel_fwd_kernel<<<blocks, 128>>>(ro, rd, density, sh, out, R);
}

// round 3
// speedup vs baseline: 3.1045x; 1.7479x over previous
#include <cuda_runtime.h>

// Plenoxel forward: R=4096 rays, S=128 samples/ray, 160^3 grid.
// d_in[0] ray_origins float32[R,3], d_in[1] ray_directions float32[R,3],
// d_in[2] density float32[160^3], d_in[3] sh_coeffs float32[160^3,3,9]
// out: concat(rgb[R,3], depth[R], acc[R])

#define GRES        160
#define NSAMP       128
#define T_NEAR      0.1f
#define T_FAR       10.0f
#define FULLMASK    0xffffffffu
#define SH_CHUNKS   ((GRES*GRES*GRES*27)/4)     // 27,648,000 float4 chunks
#define LAST_CHUNK  (SH_CHUNKS - 1)

// Branch-free accumulate of wgt * (SH_row(idx) . basis) into 3 channels.
// Row = floats [27*idx, 27*idx+27). Loads the aligned 8-float4 window and
// de-aligns with a 2-stage select tree (uniform control flow, no divergence).
__device__ __forceinline__ void sh_row_accum(const float4* __restrict__ sh4, int idx,
                                             const float (&b)[9], float wgt,
                                             float& c0, float& c1, float& c2)
{
    const int F    = idx * 27;
    const int base = F >> 2;
    const int O    = F & 3;

    float v[32];
    #pragma unroll
    for (int i = 0; i < 7; i++) {
        const float4 q = __ldg(sh4 + base + i);
        v[4*i+0] = q.x; v[4*i+1] = q.y; v[4*i+2] = q.z; v[4*i+3] = q.w;
    }
    {   // 8th chunk: only meaningful when O>=2; clamp keeps the address in-bounds
        // (garbage lands in slots the select tree never picks).
        const float4 q = __ldg(sh4 + min(base + 7, LAST_CHUNK));
        v[28] = q.x; v[29] = q.y; v[30] = q.z; v[31] = q.w;
    }

    const bool s2 = (O & 2) != 0;
    const bool s1 = (O & 1) != 0;

    float w[28];
    #pragma unroll
    for (int i = 0; i < 28; i++) w[i] = s2 ? v[i+2] : v[i];

    float d0 = 0.f, d1 = 0.f, d2 = 0.f;
    #pragma unroll
    for (int j = 0; j < 9; j++) {
        const float bj = b[j];
        const float r0 = s1 ? w[j+1]  : w[j];
        const float r1 = s1 ? w[j+10] : w[j+9];
        const float r2 = s1 ? w[j+19] : w[j+18];
        d0 = fmaf(r0, bj, d0);
        d1 = fmaf(r1, bj, d1);
        d2 = fmaf(r2, bj, d2);
    }
    c0 = fmaf(wgt, d0, c0);
    c1 = fmaf(wgt, d1, c1);
    c2 = fmaf(wgt, d2, c2);
}

__global__ __launch_bounds__(256) void plenoxel_fwd_kernel(
    const float* __restrict__ ro,
    const float* __restrict__ rd,
    const float* __restrict__ density,
    const float* __restrict__ sh,
    float* __restrict__ out,
    int R)
{
    const float4* __restrict__ sh4 = (const float4*)sh;

    const int warp = threadIdx.x >> 5;      // 0..7
    const int lane = threadIdx.x & 31;
    const int rib  = warp >> 2;              // ray-in-block 0..1
    const int wir  = warp & 3;               // warp-in-ray  0..3
    const int r    = min(blockIdx.x * 2 + rib, R - 1);

    __shared__ float sProd[2][4];
    __shared__ float sPart[2][4][5];

    const float ox = ro[r*3+0], oy = ro[r*3+1], oz = ro[r*3+2];
    const float dx = rd[r*3+0], dy = rd[r*3+1], dz = rd[r*3+2];

    const float dnorm = sqrtf(dx*dx + dy*dy + dz*dz);
    const float inv   = 1.0f / (dnorm + 1e-8f);
    const float nx = dx*inv, ny = dy*inv, nz = dz*inv;

    float b[9];
    b[0] =  0.28209479177387814f;
    b[1] = -0.48860251190291987f * ny;
    b[2] =  0.48860251190291987f * nz;
    b[3] = -0.48860251190291987f * nx;
    b[4] =  1.0925484305920792f  * nx * ny;
    b[5] = -1.0925484305920792f  * ny * nz;
    b[6] =  0.31539156525252005f * (2.0f*nz*nz - nx*nx - ny*ny);
    b[7] = -1.0925484305920792f  * nx * nz;
    b[8] =  0.5462742152960396f  * (nx*nx - ny*ny);

    const float dt = (T_FAR - T_NEAR) / (float)(NSAMP - 1);

    // --- one sample per lane ---
    const int   s = wir * 32 + lane;
    const float t = T_NEAR + dt * (float)s;

    float vx = (ox + t*dx + 1.0f) * 80.0f;
    float vy = (oy + t*dy + 1.0f) * 80.0f;
    float vz = (oz + t*dz + 1.0f) * 80.0f;
    vx = fminf(fmaxf(vx, 0.0f), 159.0f);
    vy = fminf(fmaxf(vy, 0.0f), 159.0f);
    vz = fminf(fmaxf(vz, 0.0f), 159.0f);

    const float fx = floorf(vx), fy = floorf(vy), fz = floorf(vz);
    const int x0 = (int)fx, y0 = (int)fy, z0 = (int)fz;
    const int x1 = min(x0 + 1, GRES - 1);
    const int y1 = min(y0 + 1, GRES - 1);
    const int z1 = min(z0 + 1, GRES - 1);
    const float ddx = vx - fx, ddy = vy - fy, ddz = vz - fz;
    const float wx0 = 1.0f - ddx, wx1 = ddx;
    const int   xd  = x1 - x0;

    float dens = 0.0f, c0 = 0.0f, c1 = 0.0f, c2 = 0.0f;

    #pragma unroll 1
    for (int cz = 0; cz < 2; cz++) {
        const int   zi = cz ? z1 : z0;
        const float wz = cz ? ddz : (1.0f - ddz);
        #pragma unroll 1
        for (int cy = 0; cy < 2; cy++) {
            const int   yi  = cy ? y1 : y0;
            const float wy  = cy ? ddy : (1.0f - ddy);
            const float wyz = wz * wy;
            const int idx0 = (zi * GRES + yi) * GRES + x0;
            const int idx1 = idx0 + xd;

            dens = fmaf(wyz,
                        fmaf(wx0, __ldg(density + idx0), wx1 * __ldg(density + idx1)),
                        dens);
            sh_row_accum(sh4, idx0, b, wyz * wx0, c0, c1, c2);
            sh_row_accum(sh4, idx1, b, wyz * wx1, c0, c1, c2);
        }
    }

    // colors (fast-math transcendentals; error ~2^-21 << 1e-3 tolerance)
    const float col0 = __fdividef(1.0f, 1.0f + __expf(-c0));
    const float col1 = __fdividef(1.0f, 1.0f + __expf(-c1));
    const float col2 = __fdividef(1.0f, 1.0f + __expf(-c2));

    const float dist  = ((s == NSAMP - 1) ? 1e10f : dt) * dnorm;
    const float alpha = 1.0f - __expf(-fmaxf(dens, 0.0f) * dist);

    // warp-local exclusive cumprod of (1 - alpha + 1e-10)
    float incl = 1.0f - alpha + 1e-10f;
    #pragma unroll
    for (int o = 1; o < 32; o <<= 1) {
        const float pv = __shfl_up_sync(FULLMASK, incl, o);
        if (lane >= o) incl *= pv;
    }
    float excl = __shfl_up_sync(FULLMASK, incl, 1);
    if (lane == 0) excl = 1.0f;
    const float warpProd = __shfl_sync(FULLMASK, incl, 31);

    const float w = alpha * excl;
    float rgb0 = w * col0;
    float rgb1 = w * col1;
    float rgb2 = w * col2;
    float dep  = w * t;
    float acc  = w;

    #pragma unroll
    for (int o = 16; o > 0; o >>= 1) {
        rgb0 += __shfl_xor_sync(FULLMASK, rgb0, o);
        rgb1 += __shfl_xor_sync(FULLMASK, rgb1, o);
        rgb2 += __shfl_xor_sync(FULLMASK, rgb2, o);
        dep  += __shfl_xor_sync(FULLMASK, dep,  o);
        acc  += __shfl_xor_sync(FULLMASK, acc,  o);
    }

    if (lane == 0) {
        sPart[rib][wir][0] = rgb0;
        sPart[rib][wir][1] = rgb1;
        sPart[rib][wir][2] = rgb2;
        sPart[rib][wir][3] = dep;
        sPart[rib][wir][4] = acc;
        sProd[rib][wir]    = warpProd;
    }
    __syncthreads();

    // one thread per ray composes the 4 warp segments
    if (wir == 0 && lane == 0) {
        float P = 1.0f;
        float o0 = 0.f, o1 = 0.f, o2 = 0.f, od = 0.f, oa = 0.f;
        #pragma unroll
        for (int ws = 0; ws < 4; ws++) {
            o0 += P * sPart[rib][ws][0];
            o1 += P * sPart[rib][ws][1];
            o2 += P * sPart[rib][ws][2];
            od += P * sPart[rib][ws][3];
            oa += P * sPart[rib][ws][4];
            P  *= sProd[rib][ws];
        }
        out[r*3 + 0] = o0;
        out[r*3 + 1] = o1;
        out[r*3 + 2] = o2;
        out[R*3 + r] = od;
        out[R*4 + r] = oa;
    }
}

extern "C" void kernel_launch(void* const* d_in, const int* in_sizes, int n_in,
                              void* d_out, int out_size)
{
    const float* ro      = (const float*)d_in[0];
    const float* rd      = (const float*)d_in[1];
    const float* density = (const float*)d_in[2];
    const float* sh      = (const float*)d_in[3];
    float* out           = (float*)d_out;

    const int R = in_sizes[0] / 3;      // 4096
    const int blocks = (R + 1) / 2;     // 2 rays (8 warps) per 256-thread block

    plenoxel_fwd_kernel<<<blocks, 256>>>(ro, rd, density, sh, out, R);
}

// round 4
// speedup vs baseline: 3.4687x; 1.1173x over previous
#include <cuda_runtime.h>

// Plenoxel forward: R=4096 rays, S=128 samples/ray, 160^3 grid.
// d_in[0] ray_origins float32[R,3], d_in[1] ray_directions float32[R,3],
// d_in[2] density float32[160^3], d_in[3] sh_coeffs float32[160^3,3,9]
// out: concat(rgb[R,3], depth[R], acc[R])

#define GRES        160
#define NSAMP       128
#define T_NEAR      0.1f
#define T_FAR       10.0f
#define FULLMASK    0xffffffffu

// Accumulate wgt * (SH_row(idx) . basis) into 3 channels, branch-free.
// Loads the aligned float4 window covering the 27-float row, then shifts the
// BASIS (9 floats -> 12-slot zero-padded, ~23 SELs) instead of de-aligning the
// 28-float data window (~55 SELs). Channel dots use fixed register indices.
__device__ __forceinline__ void sh_row_accum(const float4* __restrict__ sh4, int idx,
                                             const float (&b)[9], float wgt,
                                             float& c0, float& c1, float& c2)
{
    const int F    = idx * 27;
    const int base = F >> 2;
    const int O    = F & 3;
    const bool s2  = (O & 2) != 0;
    const bool s1  = (O & 1) != 0;

    float v[32];
    #pragma unroll
    for (int i = 0; i < 7; i++) {
        const float4 q = __ldg(sh4 + base + i);
        v[4*i+0] = q.x; v[4*i+1] = q.y; v[4*i+2] = q.z; v[4*i+3] = q.w;
    }
    // 8th chunk only needed (and only in-bounds-required) when O>=2; slots
    // v[28..29] multiply zero bshift entries otherwise.
    {
        float4 q = make_float4(0.f, 0.f, 0.f, 0.f);
        if (s2) q = __ldg(sh4 + base + 7);
        v[28] = q.x; v[29] = q.y; v[30] = q.z; v[31] = q.w;
    }

    // bshift[k] = (0 <= k-O < 9) ? b[k-O] : 0   via two compile-time-indexed stages
    float t[12];
    t[0]  = s2 ? 0.f  : b[0];
    t[1]  = s2 ? 0.f  : b[1];
    #pragma unroll
    for (int k = 2; k <= 8; k++) t[k] = s2 ? b[k-2] : b[k];
    t[9]  = s2 ? b[7] : 0.f;
    t[10] = s2 ? b[8] : 0.f;
    t[11] = 0.f;

    float bs[12];
    bs[0] = s1 ? 0.f : t[0];
    #pragma unroll
    for (int k = 1; k < 12; k++) bs[k] = s1 ? t[k-1] : t[k];

    float d0 = 0.f, d1 = 0.f, d2 = 0.f;
    #pragma unroll
    for (int k = 0; k < 12; k++) {
        const float bk = bs[k];
        d0 = fmaf(v[k],      bk, d0);
        d1 = fmaf(v[9 + k],  bk, d1);
        d2 = fmaf(v[18 + k], bk, d2);
    }
    c0 = fmaf(wgt, d0, c0);
    c1 = fmaf(wgt, d1, c1);
    c2 = fmaf(wgt, d2, c2);
}

__global__ __launch_bounds__(256) void plenoxel_fwd_kernel(
    const float* __restrict__ ro,
    const float* __restrict__ rd,
    const float* __restrict__ density,
    const float* __restrict__ sh,
    float* __restrict__ out,
    int R)
{
    const float4* __restrict__ sh4 = (const float4*)sh;

    const int warp = threadIdx.x >> 5;      // 0..7
    const int lane = threadIdx.x & 31;
    const int rib  = warp >> 2;              // ray-in-block 0..1
    const int wir  = warp & 3;               // warp-in-ray  0..3
    const int r    = min(blockIdx.x * 2 + rib, R - 1);

    __shared__ float sProd[2][4];
    __shared__ float sPart[2][4][5];

    const float ox = ro[r*3+0], oy = ro[r*3+1], oz = ro[r*3+2];
    const float dx = rd[r*3+0], dy = rd[r*3+1], dz = rd[r*3+2];

    const float dnorm = sqrtf(dx*dx + dy*dy + dz*dz);
    const float inv   = 1.0f / (dnorm + 1e-8f);
    const float nx = dx*inv, ny = dy*inv, nz = dz*inv;

    float b[9];
    b[0] =  0.28209479177387814f;
    b[1] = -0.48860251190291987f * ny;
    b[2] =  0.48860251190291987f * nz;
    b[3] = -0.48860251190291987f * nx;
    b[4] =  1.0925484305920792f  * nx * ny;
    b[5] = -1.0925484305920792f  * ny * nz;
    b[6] =  0.31539156525252005f * (2.0f*nz*nz - nx*nx - ny*ny);
    b[7] = -1.0925484305920792f  * nx * nz;
    b[8] =  0.5462742152960396f  * (nx*nx - ny*ny);

    const float dt = (T_FAR - T_NEAR) / (float)(NSAMP - 1);

    // --- one sample per lane ---
    const int   s = wir * 32 + lane;
    const float t = T_NEAR + dt * (float)s;

    float vx = (ox + t*dx + 1.0f) * 80.0f;
    float vy = (oy + t*dy + 1.0f) * 80.0f;
    float vz = (oz + t*dz + 1.0f) * 80.0f;
    vx = fminf(fmaxf(vx, 0.0f), 159.0f);
    vy = fminf(fmaxf(vy, 0.0f), 159.0f);
    vz = fminf(fmaxf(vz, 0.0f), 159.0f);

    const float fx = floorf(vx), fy = floorf(vy), fz = floorf(vz);
    const int x0 = (int)fx, y0 = (int)fy, z0 = (int)fz;
    const int x1 = min(x0 + 1, GRES - 1);
    const int y1 = min(y0 + 1, GRES - 1);
    const int z1 = min(z0 + 1, GRES - 1);
    const float ddx = vx - fx, ddy = vy - fy, ddz = vz - fz;
    const float wx0 = 1.0f - ddx, wx1 = ddx;
    const int   xd  = x1 - x0;

    float dens = 0.0f, c0 = 0.0f, c1 = 0.0f, c2 = 0.0f;

    #pragma unroll 1
    for (int cz = 0; cz < 2; cz++) {
        const int   zi = cz ? z1 : z0;
        const float wz = cz ? ddz : (1.0f - ddz);
        #pragma unroll 1
        for (int cy = 0; cy < 2; cy++) {
            const int   yi  = cy ? y1 : y0;
            const float wy  = cy ? ddy : (1.0f - ddy);
            const float wyz = wz * wy;
            const int idx0 = (zi * GRES + yi) * GRES + x0;
            const int idx1 = idx0 + xd;

            dens = fmaf(wyz,
                        fmaf(wx0, __ldg(density + idx0), wx1 * __ldg(density + idx1)),
                        dens);
            sh_row_accum(sh4, idx0, b, wyz * wx0, c0, c1, c2);
            sh_row_accum(sh4, idx1, b, wyz * wx1, c0, c1, c2);
        }
    }

    // colors (fast-math transcendentals; error ~2^-21 << 1e-3 tolerance)
    const float col0 = __fdividef(1.0f, 1.0f + __expf(-c0));
    const float col1 = __fdividef(1.0f, 1.0f + __expf(-c1));
    const float col2 = __fdividef(1.0f, 1.0f + __expf(-c2));

    const float dist  = ((s == NSAMP - 1) ? 1e10f : dt) * dnorm;
    const float alpha = 1.0f - __expf(-fmaxf(dens, 0.0f) * dist);

    // warp-local exclusive cumprod of (1 - alpha + 1e-10)
    float incl = 1.0f - alpha + 1e-10f;
    #pragma unroll
    for (int o = 1; o < 32; o <<= 1) {
        const float pv = __shfl_up_sync(FULLMASK, incl, o);
        if (lane >= o) incl *= pv;
    }
    float excl = __shfl_up_sync(FULLMASK, incl, 1);
    if (lane == 0) excl = 1.0f;
    const float warpProd = __shfl_sync(FULLMASK, incl, 31);

    const float w = alpha * excl;
    float rgb0 = w * col0;
    float rgb1 = w * col1;
    float rgb2 = w * col2;
    float dep  = w * t;
    float acc  = w;

    #pragma unroll
    for (int o = 16; o > 0; o >>= 1) {
        rgb0 += __shfl_xor_sync(FULLMASK, rgb0, o);
        rgb1 += __shfl_xor_sync(FULLMASK, rgb1, o);
        rgb2 += __shfl_xor_sync(FULLMASK, rgb2, o);
        dep  += __shfl_xor_sync(FULLMASK, dep,  o);
        acc  += __shfl_xor_sync(FULLMASK, acc,  o);
    }

    if (lane == 0) {
        sPart[rib][wir][0] = rgb0;
        sPart[rib][wir][1] = rgb1;
        sPart[rib][wir][2] = rgb2;
        sPart[rib][wir][3] = dep;
        sPart[rib][wir][4] = acc;
        sProd[rib][wir]    = warpProd;
    }
    __syncthreads();

    // one thread per ray composes the 4 warp segments
    if (wir == 0 && lane == 0) {
        float P = 1.0f;
        float o0 = 0.f, o1 = 0.f, o2 = 0.f, od = 0.f, oa = 0.f;
        #pragma unroll
        for (int ws = 0; ws < 4; ws++) {
            o0 += P * sPart[rib][ws][0];
            o1 += P * sPart[rib][ws][1];
            o2 += P * sPart[rib][ws][2];
            od += P * sPart[rib][ws][3];
            oa += P * sPart[rib][ws][4];
            P  *= sProd[rib][ws];
        }
        out[r*3 + 0] = o0;
        out[r*3 + 1] = o1;
        out[r*3 + 2] = o2;
        out[R*3 + r] = od;
        out[R*4 + r] = oa;
    }
}

extern "C" void kernel_launch(void* const* d_in, const int* in_sizes, int n_in,
                              void* d_out, int out_size)
{
    const float* ro      = (const float*)d_in[0];
    const float* rd      = (const float*)d_in[1];
    const float* density = (const float*)d_in[2];
    const float* sh      = (const float*)d_in[3];
    float* out           = (float*)d_out;

    const int R = in_sizes[0] / 3;      // 4096
    const int blocks = (R + 1) / 2;     // 2 rays (8 warps) per 256-thread block

    plenoxel_fwd_kernel<<<blocks, 256>>>(ro, rd, density, sh, out, R);
}